// round 11
// baseline (speedup 1.0000x reference)
#include <cuda_runtime.h>
#include <cuda_bf16.h>
#include <math.h>
#include <stdint.h>

#define BB 4
#define NN 2048
#define DD 1024
#define RR 64
#define LN_EPS 1e-5f

// ---------------- scratch (device globals; allocation-free) ----------------
__device__ __align__(128) __nv_bfloat16 g_Qb[BB * NN * RR];          // 1 MB (mask & rs folded)
__device__ __align__(128) __nv_bfloat16 g_Kb[BB * NN * RR];          // 1 MB (mask folded)
__device__ __align__(128) __nv_bfloat16 g_Eb[(size_t)BB * NN * NN];  // 32 MB exp(s) bf16
__device__ __align__(128) __nv_bfloat16 g_xb[(size_t)BB * NN * DD];  // 16 MB x bf16
__device__ __align__(128) __nv_bfloat16 g_Wb[DD * 128];              // 256 KB [U|V] bf16
__device__ float g_Lp[16][BB * NN];                                  // partials, [nblk][token]
__device__ float g_L[BB * NN];                                       // 1/rowsum
__device__ float g_rs[BB * NN];                                      // rsqrt(max(sum mask,1))
__device__ int   g_cnt[BB * 16];                                     // per (b, qblk) arrival counter

// ---------------- PTX helpers (sm_103 base ISA; no tcgen05) ----------------
__device__ __forceinline__ uint32_t smem_u32(const void* p) {
    uint32_t a;
    asm("{ .reg .u64 t; cvta.to.shared.u64 t, %1; cvt.u32.u64 %0, t; }" : "=r"(a) : "l"(p));
    return a;
}

#define LDSM_X4(r, a) \
    asm volatile("ldmatrix.sync.aligned.m8n8.x4.shared.b16 {%0,%1,%2,%3}, [%4];" \
        : "=r"((r)[0]), "=r"((r)[1]), "=r"((r)[2]), "=r"((r)[3]) : "r"(a))
#define LDSM_X4T(r, a) \
    asm volatile("ldmatrix.sync.aligned.m8n8.x4.trans.shared.b16 {%0,%1,%2,%3}, [%4];" \
        : "=r"((r)[0]), "=r"((r)[1]), "=r"((r)[2]), "=r"((r)[3]) : "r"(a))
#define MMA16816(c, a, b0, b1) \
    asm volatile("mma.sync.aligned.m16n8k16.row.col.f32.bf16.bf16.f32 " \
        "{%0,%1,%2,%3}, {%4,%5,%6,%7}, {%8,%9}, {%0,%1,%2,%3};" \
        : "+f"((c)[0]), "+f"((c)[1]), "+f"((c)[2]), "+f"((c)[3]) \
        : "r"((a)[0]), "r"((a)[1]), "r"((a)[2]), "r"((a)[3]), "r"(b0), "r"(b1))
#define CP_ASYNC16(dst, src) \
    asm volatile("cp.async.cg.shared.global [%0], [%1], 16;" :: "r"(dst), "l"(src))
#define CP_COMMIT() asm volatile("cp.async.commit_group;")
#define CP_WAIT2()  asm volatile("cp.async.wait_group 2;")

// SW128 swizzle for 128B rows (bits[4:6] ^= bits[7:9])
#define SWZ(off)  ((off) ^ (((off) >> 3) & 0x70))
// swizzle for 256B rows: 16B-chunk low-3 ^= k-row&7
#define BSWZ(off) ((off) ^ ((((off) >> 8) & 7) << 4))

// ---------------- block reductions ----------------
__device__ __forceinline__ float block_sum(float v) {
    __shared__ float red_s[8];
    #pragma unroll
    for (int o = 16; o; o >>= 1) v += __shfl_xor_sync(0xffffffffu, v, o);
    if ((threadIdx.x & 31) == 0) red_s[threadIdx.x >> 5] = v;
    __syncthreads();
    float r = 0.f;
    #pragma unroll
    for (int i = 0; i < 8; i++) r += red_s[i];
    __syncthreads();
    return r;
}

// ---------------- K0: fused preamble: x->bf16 | reff | [U|V]->bf16 ----------------
#define XB_BLOCKS (BB * NN * DD / 4 / 256)   // 8192
#define RF_BLOCKS (BB * NN / 8)              // 1024
#define WC_BLOCKS 128

__global__ __launch_bounds__(256) void k_prep(const float* __restrict__ x,
                                              const float* __restrict__ mask,
                                              const float* __restrict__ U,
                                              const float* __restrict__ V) {
    int bidx = blockIdx.x;
    if (bidx < XB_BLOCKS) {
        size_t i = (size_t)bidx * 256 + threadIdx.x;   // float4 index
        float4 v = *((const float4*)x + i);
        __nv_bfloat162* o = (__nv_bfloat162*)g_xb + i * 2;
        o[0] = __float22bfloat162_rn(make_float2(v.x, v.y));
        o[1] = __float22bfloat162_rn(make_float2(v.z, v.w));
    } else if (bidx < XB_BLOCKS + RF_BLOCKS) {
        int t = (bidx - XB_BLOCKS) * 8 + (threadIdx.x >> 5);
        int lane = threadIdx.x & 31;
        float v = mask[t * RR + lane] + mask[t * RR + 32 + lane];
        #pragma unroll
        for (int o = 16; o; o >>= 1) v += __shfl_xor_sync(0xffffffffu, v, o);
        if (lane == 0) g_rs[t] = rsqrtf(fmaxf(v, 1.0f));
    } else {
        int i = (bidx - XB_BLOCKS - RF_BLOCKS) * 256 + threadIdx.x;  // float4 slots
        int half = i >> 14;
        int j = i & 16383;
        int k = j >> 4, r4 = (j & 15) * 4;
        const float* src = half ? V : U;
        float4 v = *(const float4*)&src[k * RR + r4];
        __nv_bfloat162* o = (__nv_bfloat162*)&g_Wb[k * 128 + half * 64 + r4];
        o[0] = __float22bfloat162_rn(make_float2(v.x, v.y));
        o[1] = __float22bfloat162_rn(make_float2(v.z, v.w));
    }
}

// ---------------- K1: [Q|K] = x @ [U|V] (bf16 MMA), CTA 64x128, 8 warps 2m x 4n ----------------
#define PSTAGE 24576              // A 8KB (64x64) + B 16KB (64x128)
#define PSMEM (3 * PSTAGE)        // 72 KB

__device__ __forceinline__ void proj_load_stage(uint32_t st, const __nv_bfloat16* A,
                                                int kc, int tid) {
    #pragma unroll
    for (int i = 0; i < 2; i++) {
        int idx = tid + i * 256;
        int m = idx >> 3, ch = idx & 7;
        uint32_t dst = st + SWZ((uint32_t)(m * 128 + ch * 16));
        CP_ASYNC16(dst, A + (size_t)m * DD + kc + ch * 8);
    }
    #pragma unroll
    for (int i = 0; i < 4; i++) {
        int idx = tid + i * 256;
        int k = idx >> 4, ch = idx & 15;
        uint32_t dst = st + 8192 + BSWZ((uint32_t)(k * 256 + ch * 16));
        CP_ASYNC16(dst, g_Wb + (size_t)(kc + k) * 128 + ch * 8);
    }
}

__global__ __launch_bounds__(256) void k_proj_mma(const float* __restrict__ mask) {
    extern __shared__ __align__(128) char smem[];
    uint32_t sb = smem_u32(smem);
    int tid = threadIdx.x;
    int lane = tid & 31, wid = tid >> 5;
    int warp_m = wid & 1, warp_n = wid >> 1;
    int m0 = blockIdx.y * 64;

    const __nv_bfloat16* A = g_xb + (size_t)m0 * DD;
    float acc[2][4][4] = {};
    const int PNC = DD / 64;   // 16

    proj_load_stage(sb, A, 0, tid);  CP_COMMIT();
    proj_load_stage(sb + PSTAGE, A, 64, tid);  CP_COMMIT();
    proj_load_stage(sb + 2 * PSTAGE, A, 128, tid);  CP_COMMIT();

    for (int c = 0; c < PNC; c++) {
        CP_WAIT2();
        __syncthreads();
        uint32_t stA = sb + (c % 3) * PSTAGE;
        uint32_t stB = stA + 8192;
        #pragma unroll
        for (int ks = 0; ks < 4; ks++) {
            uint32_t a[2][4];
            #pragma unroll
            for (int mt = 0; mt < 2; mt++) {
                int row = warp_m * 32 + mt * 16 + (lane & 15);
                uint32_t addr = stA + SWZ((uint32_t)(row * 128 + ks * 32 + (lane >> 4) * 16));
                LDSM_X4(a[mt], addr);
            }
            uint32_t bf[2][4];
            #pragma unroll
            for (int np = 0; np < 2; np++) {
                int k = ks * 16 + (lane & 15);
                int n = warp_n * 32 + np * 16 + (lane >> 4) * 8;
                uint32_t addr = stB + BSWZ((uint32_t)(k * 256 + n * 2));
                LDSM_X4T(bf[np], addr);
            }
            #pragma unroll
            for (int mt = 0; mt < 2; mt++)
                #pragma unroll
                for (int nt = 0; nt < 4; nt++) {
                    int np = nt >> 1, o = (nt & 1) * 2;
                    MMA16816(acc[mt][nt], a[mt], bf[np][o], bf[np][o + 1]);
                }
        }
        __syncthreads();
        if (c + 3 < PNC) {
            proj_load_stage(sb + (c % 3) * PSTAGE, A, (c + 3) * 64, tid);
            CP_COMMIT();
        }
    }

    #pragma unroll
    for (int mt = 0; mt < 2; mt++) {
        int t0 = m0 + warp_m * 32 + mt * 16 + (lane >> 2);
        int t1 = t0 + 8;
        float rs0 = g_rs[t0], rs1 = g_rs[t1];
        #pragma unroll
        for (int nt = 0; nt < 4; nt++) {
            int c = warp_n * 32 + nt * 8 + (lane & 3) * 2;
            if (c < 64) {
                float2 mk0 = *(const float2*)&mask[(size_t)t0 * RR + c];
                float2 mk1 = *(const float2*)&mask[(size_t)t1 * RR + c];
                *(__nv_bfloat162*)&g_Qb[(size_t)t0 * RR + c] = __float22bfloat162_rn(
                    make_float2(acc[mt][nt][0] * mk0.x * rs0, acc[mt][nt][1] * mk0.y * rs0));
                *(__nv_bfloat162*)&g_Qb[(size_t)t1 * RR + c] = __float22bfloat162_rn(
                    make_float2(acc[mt][nt][2] * mk1.x * rs1, acc[mt][nt][3] * mk1.y * rs1));
            } else {
                int c2 = c - 64;
                float2 mk0 = *(const float2*)&mask[(size_t)t0 * RR + c2];
                float2 mk1 = *(const float2*)&mask[(size_t)t1 * RR + c2];
                *(__nv_bfloat162*)&g_Kb[(size_t)t0 * RR + c2] = __float22bfloat162_rn(
                    make_float2(acc[mt][nt][0] * mk0.x, acc[mt][nt][1] * mk0.y));
                *(__nv_bfloat162*)&g_Kb[(size_t)t1 * RR + c2] = __float22bfloat162_rn(
                    make_float2(acc[mt][nt][2] * mk1.x, acc[mt][nt][3] * mk1.y));
            }
        }
    }
}

// ---------------- K2: E = exp(Q @ K^T), partials + fused last-CTA row-sum reduction ----------------
__global__ __launch_bounds__(256) void k_scores_mma() {
    __shared__ __align__(128) char smem[32768];   // A 16KB + B 16KB
    __shared__ float ssum[4][128];
    __shared__ int s_last;
    uint32_t sb = smem_u32(smem);
    int tid = threadIdx.x;
    int lane = tid & 31, wid = tid >> 5;
    int warp_m = wid & 1, warp_n = wid >> 1;
    int b = blockIdx.z;
    int q0 = blockIdx.y * 128, n0 = blockIdx.x * 128;

    const __nv_bfloat16* Qb = g_Qb + ((size_t)b * NN + q0) * RR;
    const __nv_bfloat16* Kb = g_Kb + ((size_t)b * NN + n0) * RR;
    uint32_t sA = sb, sB = sb + 16384;

    #pragma unroll
    for (int i = 0; i < 4; i++) {
        int idx = tid + i * 256;
        int row = idx >> 3, ch = idx & 7;
        uint4 v = *(const uint4*)&Qb[row * RR + ch * 8];
        uint32_t off = SWZ((uint32_t)(row * 128 + ch * 16));
        asm volatile("st.shared.v4.b32 [%0], {%1,%2,%3,%4};"
                     :: "r"(sA + off), "r"(v.x), "r"(v.y), "r"(v.z), "r"(v.w) : "memory");
        uint4 w = *(const uint4*)&Kb[row * RR + ch * 8];
        asm volatile("st.shared.v4.b32 [%0], {%1,%2,%3,%4};"
                     :: "r"(sB + off), "r"(w.x), "r"(w.y), "r"(w.z), "r"(w.w) : "memory");
    }
    __syncthreads();

    float acc[4][4][4] = {};
    #pragma unroll
    for (int ks = 0; ks < 4; ks++) {
        uint32_t a[4][4];
        #pragma unroll
        for (int mt = 0; mt < 4; mt++) {
            int row = warp_m * 64 + mt * 16 + (lane & 15);
            uint32_t addr = sA + SWZ((uint32_t)(row * 128 + ks * 32 + (lane >> 4) * 16));
            LDSM_X4(a[mt], addr);
        }
        uint32_t bf[2][4];
        #pragma unroll
        for (int np = 0; np < 2; np++) {
            int row = warp_n * 32 + np * 16 + (lane & 15);
            uint32_t addr = sB + SWZ((uint32_t)(row * 128 + ks * 32 + (lane >> 4) * 16));
            LDSM_X4(bf[np], addr);
        }
        #pragma unroll
        for (int mt = 0; mt < 4; mt++)
            #pragma unroll
            for (int nt = 0; nt < 4; nt++) {
                int np = nt >> 1, o = nt & 1;
                MMA16816(acc[mt][nt], a[mt], bf[np][o], bf[np][o + 2]);
            }
    }

    __nv_bfloat16* Eb = g_Eb + (size_t)b * NN * NN;
    #pragma unroll
    for (int mt = 0; mt < 4; mt++) {
        int r0 = warp_m * 64 + mt * 16 + (lane >> 2);
        int r1 = r0 + 8;
        float s0 = 0.f, s1 = 0.f;
        #pragma unroll
        for (int nt = 0; nt < 4; nt++) {
            int col = n0 + warp_n * 32 + nt * 8 + (lane & 3) * 2;
            float e0 = __expf(acc[mt][nt][0]);
            float e1 = __expf(acc[mt][nt][1]);
            float e2 = __expf(acc[mt][nt][2]);
            float e3 = __expf(acc[mt][nt][3]);
            s0 += e0 + e1; s1 += e2 + e3;
            *(__nv_bfloat162*)&Eb[(size_t)(q0 + r0) * NN + col] =
                __float22bfloat162_rn(make_float2(e0, e1));
            *(__nv_bfloat162*)&Eb[(size_t)(q0 + r1) * NN + col] =
                __float22bfloat162_rn(make_float2(e2, e3));
        }
        s0 += __shfl_xor_sync(0xffffffffu, s0, 1);
        s0 += __shfl_xor_sync(0xffffffffu, s0, 2);
        s1 += __shfl_xor_sync(0xffffffffu, s1, 1);
        s1 += __shfl_xor_sync(0xffffffffu, s1, 2);
        if ((lane & 3) == 0) {
            ssum[warp_n][r0] = s0;
            ssum[warp_n][r1] = s1;
        }
    }
    __syncthreads();
    if (tid < 128) {
        float s = ssum[0][tid] + ssum[1][tid] + ssum[2][tid] + ssum[3][tid];
        g_Lp[blockIdx.x][(size_t)b * NN + q0 + tid] = s;   // coalesced: [nblk][token]
    }
    // last CTA of this (b, qblk) row group reduces the 16 partials
    __threadfence();
    __syncthreads();
    if (tid == 0) {
        int g = b * 16 + blockIdx.y;
        s_last = (atomicAdd(&g_cnt[g], 1) == 15) ? 1 : 0;
        if (s_last) g_cnt[g] = 0;   // self-reset for next launch/replay
    }
    __syncthreads();
    if (s_last) {
        __threadfence();            // acquire: make all partials visible
        if (tid < 128) {
            int t = b * NN + q0 + tid;
            float s = 0.f;
            #pragma unroll
            for (int i = 0; i < 16; i++) s += g_Lp[i][t];
            g_L[t] = 1.0f / s;
        }
    }
}

// ---------------- K4: out = x + (E @ xb)*(1/l), CTA 128x128, 4 warps 2m x 2n (64x64) ----------------
#define DK 64
#define DSTAGE 32768              // A 16KB (128x64) + B 16KB (64x128)
#define DSMEM (3 * DSTAGE)        // 96 KB

__device__ __forceinline__ void delta_load_stage(uint32_t st, const __nv_bfloat16* Eb,
                                                 const __nv_bfloat16* Xb, int kc, int tid) {
    #pragma unroll
    for (int i = 0; i < 8; i++) {
        int idx = tid + i * 128;
        int m = idx >> 3, ch = idx & 7;
        uint32_t dst = st + SWZ((uint32_t)(m * 128 + ch * 16));
        CP_ASYNC16(dst, Eb + (size_t)m * NN + kc + ch * 8);
    }
    #pragma unroll
    for (int i = 0; i < 8; i++) {
        int idx = tid + i * 128;
        int k = idx >> 4, ch = idx & 15;
        uint32_t dst = st + 16384 + BSWZ((uint32_t)(k * 256 + ch * 16));
        CP_ASYNC16(dst, Xb + (size_t)(kc + k) * DD + ch * 8);
    }
}

__global__ __launch_bounds__(128, 2) void k_delta_mma(const float* __restrict__ x,
                                                      float* __restrict__ out) {
    extern __shared__ __align__(128) char smem[];
    uint32_t sb = smem_u32(smem);
    int tid = threadIdx.x;
    int lane = tid & 31, wid = tid >> 5;
    int warp_m = wid & 1, warp_n = wid >> 1;   // 2m x 2n, warp tile 64x64
    int b = blockIdx.z;
    int q0 = blockIdx.y * 128, d0 = blockIdx.x * 128;

    const __nv_bfloat16* Eb = g_Eb + (size_t)b * NN * NN + (size_t)q0 * NN;
    const __nv_bfloat16* Xb = g_xb + (size_t)b * NN * DD + d0;
    float acc[4][8][4] = {};
    const int DNC = NN / DK;   // 32

    delta_load_stage(sb, Eb, Xb, 0, tid);  CP_COMMIT();
    delta_load_stage(sb + DSTAGE, Eb, Xb, DK, tid);  CP_COMMIT();
    delta_load_stage(sb + 2 * DSTAGE, Eb, Xb, 2 * DK, tid);  CP_COMMIT();

    for (int c = 0; c < DNC; c++) {
        CP_WAIT2();
        __syncthreads();
        uint32_t stA = sb + (c % 3) * DSTAGE;
        uint32_t stB = stA + 16384;
        #pragma unroll
        for (int ks = 0; ks < 4; ks++) {
            uint32_t a[4][4];
            #pragma unroll
            for (int mt = 0; mt < 4; mt++) {
                int row = warp_m * 64 + mt * 16 + (lane & 15);
                uint32_t addr = stA + SWZ((uint32_t)(row * 128 + ks * 32 + (lane >> 4) * 16));
                LDSM_X4(a[mt], addr);
            }
            uint32_t bf[4][4];
            #pragma unroll
            for (int np = 0; np < 4; np++) {
                int k = ks * 16 + (lane & 15);
                int n = warp_n * 64 + np * 16 + (lane >> 4) * 8;
                uint32_t addr = stB + BSWZ((uint32_t)(k * 256 + n * 2));
                LDSM_X4T(bf[np], addr);
            }
            #pragma unroll
            for (int mt = 0; mt < 4; mt++)
                #pragma unroll
                for (int nt = 0; nt < 8; nt++) {
                    int np = nt >> 1, o = (nt & 1) * 2;
                    MMA16816(acc[mt][nt], a[mt], bf[np][o], bf[np][o + 1]);
                }
        }
        __syncthreads();
        if (c + 3 < DNC) {
            delta_load_stage(sb + (c % 3) * DSTAGE, Eb, Xb, (c + 3) * DK, tid);
            CP_COMMIT();
        }
    }

    #pragma unroll
    for (int mt = 0; mt < 4; mt++) {
        int r0 = q0 + warp_m * 64 + mt * 16 + (lane >> 2);
        int r1 = r0 + 8;
        float l0 = g_L[b * NN + r0];
        float l1 = g_L[b * NN + r1];
        #pragma unroll
        for (int nt = 0; nt < 8; nt++) {
            int col = d0 + warp_n * 64 + nt * 8 + (lane & 3) * 2;
            size_t p0 = ((size_t)b * NN + r0) * DD + col;
            size_t p1 = ((size_t)b * NN + r1) * DD + col;
            float2 x0 = *(const float2*)&x[p0];
            float2 x1 = *(const float2*)&x[p1];
            *(float2*)&out[p0] = make_float2(fmaf(acc[mt][nt][0], l0, x0.x),
                                             fmaf(acc[mt][nt][1], l0, x0.y));
            *(float2*)&out[p1] = make_float2(fmaf(acc[mt][nt][2], l1, x1.x),
                                             fmaf(acc[mt][nt][3], l1, x1.y));
        }
    }
}

// ---------------- K6: in-place LayerNorm on out (float4) ----------------
__global__ __launch_bounds__(256) void k_ln(float* __restrict__ out,
                                            const float* __restrict__ gamma,
                                            const float* __restrict__ beta) {
    size_t row = blockIdx.x;
    float* y = out + row * DD;
    int tid = threadIdx.x;
    float4 v = *(float4*)&y[tid * 4];
    float mu = block_sum(v.x + v.y + v.z + v.w) * (1.0f / DD);
    float dx = v.x - mu, dy = v.y - mu, dz = v.z - mu, dw = v.w - mu;
    float var = block_sum(dx * dx + dy * dy + dz * dz + dw * dw) * (1.0f / DD);
    float inv = rsqrtf(var + LN_EPS);
    float4 g = *(const float4*)&gamma[tid * 4];
    float4 be = *(const float4*)&beta[tid * 4];
    float4 o;
    o.x = dx * inv * g.x + be.x;
    o.y = dy * inv * g.y + be.y;
    o.z = dz * inv * g.z + be.z;
    o.w = dw * inv * g.w + be.w;
    *(float4*)&y[tid * 4] = o;
}

extern "C" void kernel_launch(void* const* d_in, const int* in_sizes, int n_in,
                              void* d_out, int out_size) {
    const float* x     = (const float*)d_in[0];
    const float* mask  = (const float*)d_in[1];
    const float* U     = (const float*)d_in[2];
    const float* V     = (const float*)d_in[3];
    const float* gamma = (const float*)d_in[4];
    const float* beta  = (const float*)d_in[5];
    float* out = (float*)d_out;

    cudaFuncSetAttribute(k_proj_mma, cudaFuncAttributeMaxDynamicSharedMemorySize, PSMEM);
    cudaFuncSetAttribute(k_delta_mma, cudaFuncAttributeMaxDynamicSharedMemorySize, DSMEM);

    k_prep<<<XB_BLOCKS + RF_BLOCKS + WC_BLOCKS, 256>>>(x, mask, U, V);
    k_proj_mma<<<dim3(1, BB * NN / 64, 1), 256, PSMEM>>>(mask);
    dim3 gs(NN / 128, NN / 128, BB);
    k_scores_mma<<<gs, 256>>>();
    dim3 gd(DD / 128, NN / 128, BB);
    k_delta_mma<<<gd, 128, DSMEM>>>(x, out);
    k_ln<<<BB * NN, 256>>>(out, gamma, beta);
}

// round 13
// speedup vs baseline: 1.0877x; 1.0877x over previous
#include <cuda_runtime.h>
#include <cuda_bf16.h>
#include <math.h>
#include <stdint.h>

#define BB 4
#define NN 2048
#define DD 1024
#define RR 64
#define LN_EPS 1e-5f

// ---------------- scratch (device globals; allocation-free) ----------------
__device__ __align__(128) __nv_bfloat16 g_Qb[BB * NN * RR];          // 1 MB (mask & rs folded)
__device__ __align__(128) __nv_bfloat16 g_Kb[BB * NN * RR];          // 1 MB (mask folded)
__device__ __align__(128) __nv_bfloat16 g_Eb[(size_t)BB * NN * NN];  // 32 MB exp(s) bf16
__device__ __align__(128) __nv_bfloat16 g_xb[(size_t)BB * NN * DD];  // 16 MB x bf16
__device__ __align__(128) __nv_bfloat16 g_Wb[DD * 128];              // 256 KB [U|V] bf16
__device__ float g_Lp[16][BB * NN];                                  // partials, [nblk][token]
__device__ float g_L[BB * NN];                                       // 1/rowsum
__device__ float g_rs[BB * NN];                                      // rsqrt(max(sum mask,1))

// ---------------- PTX helpers (sm_103 base ISA; no tcgen05) ----------------
__device__ __forceinline__ uint32_t smem_u32(const void* p) {
    uint32_t a;
    asm("{ .reg .u64 t; cvta.to.shared.u64 t, %1; cvt.u32.u64 %0, t; }" : "=r"(a) : "l"(p));
    return a;
}

#define LDSM_X4(r, a) \
    asm volatile("ldmatrix.sync.aligned.m8n8.x4.shared.b16 {%0,%1,%2,%3}, [%4];" \
        : "=r"((r)[0]), "=r"((r)[1]), "=r"((r)[2]), "=r"((r)[3]) : "r"(a))
#define LDSM_X4T(r, a) \
    asm volatile("ldmatrix.sync.aligned.m8n8.x4.trans.shared.b16 {%0,%1,%2,%3}, [%4];" \
        : "=r"((r)[0]), "=r"((r)[1]), "=r"((r)[2]), "=r"((r)[3]) : "r"(a))
#define MMA16816(c, a, b0, b1) \
    asm volatile("mma.sync.aligned.m16n8k16.row.col.f32.bf16.bf16.f32 " \
        "{%0,%1,%2,%3}, {%4,%5,%6,%7}, {%8,%9}, {%0,%1,%2,%3};" \
        : "+f"((c)[0]), "+f"((c)[1]), "+f"((c)[2]), "+f"((c)[3]) \
        : "r"((a)[0]), "r"((a)[1]), "r"((a)[2]), "r"((a)[3]), "r"(b0), "r"(b1))
#define CP_ASYNC16(dst, src) \
    asm volatile("cp.async.cg.shared.global [%0], [%1], 16;" :: "r"(dst), "l"(src))
#define CP_COMMIT() asm volatile("cp.async.commit_group;")
#define CP_WAIT2()  asm volatile("cp.async.wait_group 2;")

// SW128 swizzle for 128B rows (bits[4:6] ^= bits[7:9])
#define SWZ(off)  ((off) ^ (((off) >> 3) & 0x70))
// swizzle for 256B rows: 16B-chunk low-3 ^= k-row&7
#define BSWZ(off) ((off) ^ ((((off) >> 8) & 7) << 4))

// ---------------- block reductions ----------------
__device__ __forceinline__ float block_sum(float v) {
    __shared__ float red_s[8];
    #pragma unroll
    for (int o = 16; o; o >>= 1) v += __shfl_xor_sync(0xffffffffu, v, o);
    if ((threadIdx.x & 31) == 0) red_s[threadIdx.x >> 5] = v;
    __syncthreads();
    float r = 0.f;
    #pragma unroll
    for (int i = 0; i < 8; i++) r += red_s[i];
    __syncthreads();
    return r;
}

// ---------------- K0: fused preamble: x->bf16 | reff | [U|V]->bf16 ----------------
#define XB_BLOCKS (BB * NN * DD / 4 / 256)   // 8192
#define RF_BLOCKS (BB * NN / 8)              // 1024
#define WC_BLOCKS 128

__global__ __launch_bounds__(256) void k_prep(const float* __restrict__ x,
                                              const float* __restrict__ mask,
                                              const float* __restrict__ U,
                                              const float* __restrict__ V) {
    int bidx = blockIdx.x;
    if (bidx < XB_BLOCKS) {
        size_t i = (size_t)bidx * 256 + threadIdx.x;   // float4 index
        float4 v = *((const float4*)x + i);
        __nv_bfloat162* o = (__nv_bfloat162*)g_xb + i * 2;
        o[0] = __float22bfloat162_rn(make_float2(v.x, v.y));
        o[1] = __float22bfloat162_rn(make_float2(v.z, v.w));
    } else if (bidx < XB_BLOCKS + RF_BLOCKS) {
        int t = (bidx - XB_BLOCKS) * 8 + (threadIdx.x >> 5);
        int lane = threadIdx.x & 31;
        float v = mask[t * RR + lane] + mask[t * RR + 32 + lane];
        #pragma unroll
        for (int o = 16; o; o >>= 1) v += __shfl_xor_sync(0xffffffffu, v, o);
        if (lane == 0) g_rs[t] = rsqrtf(fmaxf(v, 1.0f));
    } else {
        int i = (bidx - XB_BLOCKS - RF_BLOCKS) * 256 + threadIdx.x;  // float4 slots
        int half = i >> 14;
        int j = i & 16383;
        int k = j >> 4, r4 = (j & 15) * 4;
        const float* src = half ? V : U;
        float4 v = *(const float4*)&src[k * RR + r4];
        __nv_bfloat162* o = (__nv_bfloat162*)&g_Wb[k * 128 + half * 64 + r4];
        o[0] = __float22bfloat162_rn(make_float2(v.x, v.y));
        o[1] = __float22bfloat162_rn(make_float2(v.z, v.w));
    }
}

// ---------------- K1: [Q|K] = x @ [U|V] (bf16 MMA), CTA 64x128, 8 warps 2m x 4n ----------------
#define PSTAGE 24576              // A 8KB (64x64) + B 16KB (64x128)
#define PSMEM (3 * PSTAGE)        // 72 KB

__device__ __forceinline__ void proj_load_stage(uint32_t st, const __nv_bfloat16* A,
                                                int kc, int tid) {
    #pragma unroll
    for (int i = 0; i < 2; i++) {
        int idx = tid + i * 256;
        int m = idx >> 3, ch = idx & 7;
        uint32_t dst = st + SWZ((uint32_t)(m * 128 + ch * 16));
        CP_ASYNC16(dst, A + (size_t)m * DD + kc + ch * 8);
    }
    #pragma unroll
    for (int i = 0; i < 4; i++) {
        int idx = tid + i * 256;
        int k = idx >> 4, ch = idx & 15;
        uint32_t dst = st + 8192 + BSWZ((uint32_t)(k * 256 + ch * 16));
        CP_ASYNC16(dst, g_Wb + (size_t)(kc + k) * 128 + ch * 8);
    }
}

__global__ __launch_bounds__(256) void k_proj_mma(const float* __restrict__ mask) {
    extern __shared__ __align__(128) char smem[];
    uint32_t sb = smem_u32(smem);
    int tid = threadIdx.x;
    int lane = tid & 31, wid = tid >> 5;
    int warp_m = wid & 1, warp_n = wid >> 1;
    int m0 = blockIdx.y * 64;

    const __nv_bfloat16* A = g_xb + (size_t)m0 * DD;
    float acc[2][4][4] = {};
    const int PNC = DD / 64;   // 16

    proj_load_stage(sb, A, 0, tid);  CP_COMMIT();
    proj_load_stage(sb + PSTAGE, A, 64, tid);  CP_COMMIT();
    proj_load_stage(sb + 2 * PSTAGE, A, 128, tid);  CP_COMMIT();

    for (int c = 0; c < PNC; c++) {
        CP_WAIT2();
        __syncthreads();
        uint32_t stA = sb + (c % 3) * PSTAGE;
        uint32_t stB = stA + 8192;
        #pragma unroll
        for (int ks = 0; ks < 4; ks++) {
            uint32_t a[2][4];
            #pragma unroll
            for (int mt = 0; mt < 2; mt++) {
                int row = warp_m * 32 + mt * 16 + (lane & 15);
                uint32_t addr = stA + SWZ((uint32_t)(row * 128 + ks * 32 + (lane >> 4) * 16));
                LDSM_X4(a[mt], addr);
            }
            uint32_t bf[2][4];
            #pragma unroll
            for (int np = 0; np < 2; np++) {
                int k = ks * 16 + (lane & 15);
                int n = warp_n * 32 + np * 16 + (lane >> 4) * 8;
                uint32_t addr = stB + BSWZ((uint32_t)(k * 256 + n * 2));
                LDSM_X4T(bf[np], addr);
            }
            #pragma unroll
            for (int mt = 0; mt < 2; mt++)
                #pragma unroll
                for (int nt = 0; nt < 4; nt++) {
                    int np = nt >> 1, o = (nt & 1) * 2;
                    MMA16816(acc[mt][nt], a[mt], bf[np][o], bf[np][o + 1]);
                }
        }
        __syncthreads();
        if (c + 3 < PNC) {
            proj_load_stage(sb + (c % 3) * PSTAGE, A, (c + 3) * 64, tid);
            CP_COMMIT();
        }
    }

    #pragma unroll
    for (int mt = 0; mt < 2; mt++) {
        int t0 = m0 + warp_m * 32 + mt * 16 + (lane >> 2);
        int t1 = t0 + 8;
        float rs0 = g_rs[t0], rs1 = g_rs[t1];
        #pragma unroll
        for (int nt = 0; nt < 4; nt++) {
            int c = warp_n * 32 + nt * 8 + (lane & 3) * 2;
            if (c < 64) {
                float2 mk0 = *(const float2*)&mask[(size_t)t0 * RR + c];
                float2 mk1 = *(const float2*)&mask[(size_t)t1 * RR + c];
                *(__nv_bfloat162*)&g_Qb[(size_t)t0 * RR + c] = __float22bfloat162_rn(
                    make_float2(acc[mt][nt][0] * mk0.x * rs0, acc[mt][nt][1] * mk0.y * rs0));
                *(__nv_bfloat162*)&g_Qb[(size_t)t1 * RR + c] = __float22bfloat162_rn(
                    make_float2(acc[mt][nt][2] * mk1.x * rs1, acc[mt][nt][3] * mk1.y * rs1));
            } else {
                int c2 = c - 64;
                float2 mk0 = *(const float2*)&mask[(size_t)t0 * RR + c2];
                float2 mk1 = *(const float2*)&mask[(size_t)t1 * RR + c2];
                *(__nv_bfloat162*)&g_Kb[(size_t)t0 * RR + c2] = __float22bfloat162_rn(
                    make_float2(acc[mt][nt][0] * mk0.x, acc[mt][nt][1] * mk0.y));
                *(__nv_bfloat162*)&g_Kb[(size_t)t1 * RR + c2] = __float22bfloat162_rn(
                    make_float2(acc[mt][nt][2] * mk1.x, acc[mt][nt][3] * mk1.y));
            }
        }
    }
}

// ---------------- K2: E = exp(Q @ K^T), coalesced partial row sums ----------------
__global__ __launch_bounds__(256) void k_scores_mma() {
    __shared__ __align__(128) char smem[32768];   // A 16KB + B 16KB
    __shared__ float ssum[4][128];
    uint32_t sb = smem_u32(smem);
    int tid = threadIdx.x;
    int lane = tid & 31, wid = tid >> 5;
    int warp_m = wid & 1, warp_n = wid >> 1;
    int b = blockIdx.z;
    int q0 = blockIdx.y * 128, n0 = blockIdx.x * 128;

    const __nv_bfloat16* Qb = g_Qb + ((size_t)b * NN + q0) * RR;
    const __nv_bfloat16* Kb = g_Kb + ((size_t)b * NN + n0) * RR;
    uint32_t sA = sb, sB = sb + 16384;

    #pragma unroll
    for (int i = 0; i < 4; i++) {
        int idx = tid + i * 256;
        int row = idx >> 3, ch = idx & 7;
        uint4 v = *(const uint4*)&Qb[row * RR + ch * 8];
        uint32_t off = SWZ((uint32_t)(row * 128 + ch * 16));
        asm volatile("st.shared.v4.b32 [%0], {%1,%2,%3,%4};"
                     :: "r"(sA + off), "r"(v.x), "r"(v.y), "r"(v.z), "r"(v.w) : "memory");
        uint4 w = *(const uint4*)&Kb[row * RR + ch * 8];
        asm volatile("st.shared.v4.b32 [%0], {%1,%2,%3,%4};"
                     :: "r"(sB + off), "r"(w.x), "r"(w.y), "r"(w.z), "r"(w.w) : "memory");
    }
    __syncthreads();

    float acc[4][4][4] = {};
    #pragma unroll
    for (int ks = 0; ks < 4; ks++) {
        uint32_t a[4][4];
        #pragma unroll
        for (int mt = 0; mt < 4; mt++) {
            int row = warp_m * 64 + mt * 16 + (lane & 15);
            uint32_t addr = sA + SWZ((uint32_t)(row * 128 + ks * 32 + (lane >> 4) * 16));
            LDSM_X4(a[mt], addr);
        }
        uint32_t bf[2][4];
        #pragma unroll
        for (int np = 0; np < 2; np++) {
            int row = warp_n * 32 + np * 16 + (lane & 15);
            uint32_t addr = sB + SWZ((uint32_t)(row * 128 + ks * 32 + (lane >> 4) * 16));
            LDSM_X4(bf[np], addr);
        }
        #pragma unroll
        for (int mt = 0; mt < 4; mt++)
            #pragma unroll
            for (int nt = 0; nt < 4; nt++) {
                int np = nt >> 1, o = nt & 1;
                MMA16816(acc[mt][nt], a[mt], bf[np][o], bf[np][o + 2]);
            }
    }

    __nv_bfloat16* Eb = g_Eb + (size_t)b * NN * NN;
    #pragma unroll
    for (int mt = 0; mt < 4; mt++) {
        int r0 = warp_m * 64 + mt * 16 + (lane >> 2);
        int r1 = r0 + 8;
        float s0 = 0.f, s1 = 0.f;
        #pragma unroll
        for (int nt = 0; nt < 4; nt++) {
            int col = n0 + warp_n * 32 + nt * 8 + (lane & 3) * 2;
            float e0 = __expf(acc[mt][nt][0]);
            float e1 = __expf(acc[mt][nt][1]);
            float e2 = __expf(acc[mt][nt][2]);
            float e3 = __expf(acc[mt][nt][3]);
            s0 += e0 + e1; s1 += e2 + e3;
            *(__nv_bfloat162*)&Eb[(size_t)(q0 + r0) * NN + col] =
                __float22bfloat162_rn(make_float2(e0, e1));
            *(__nv_bfloat162*)&Eb[(size_t)(q0 + r1) * NN + col] =
                __float22bfloat162_rn(make_float2(e2, e3));
        }
        s0 += __shfl_xor_sync(0xffffffffu, s0, 1);
        s0 += __shfl_xor_sync(0xffffffffu, s0, 2);
        s1 += __shfl_xor_sync(0xffffffffu, s1, 1);
        s1 += __shfl_xor_sync(0xffffffffu, s1, 2);
        if ((lane & 3) == 0) {
            ssum[warp_n][r0] = s0;
            ssum[warp_n][r1] = s1;
        }
    }
    __syncthreads();
    if (tid < 128) {
        float s = ssum[0][tid] + ssum[1][tid] + ssum[2][tid] + ssum[3][tid];
        g_Lp[blockIdx.x][(size_t)b * NN + q0 + tid] = s;   // coalesced: [nblk][token]
    }
}

// ---------------- K2b: reduce partials (coalesced) -> g_L = 1/sum ----------------
__global__ __launch_bounds__(256) void k_lred() {
    int t = blockIdx.x * 256 + threadIdx.x;   // 0..8191
    float s = 0.f;
    #pragma unroll
    for (int i = 0; i < 16; i++) s += g_Lp[i][t];
    g_L[t] = 1.0f / s;
}

// ---------------- K4: out = x + (E @ xb)*(1/l), CTA 128x64, 4 warps 2m x 2n (64x32) ----------------
#define DK 64
#define DSTAGE 24576              // A 16KB (128x64) + B 8KB (64x64)
#define DSMEM (3 * DSTAGE)        // 72 KB -> 3 CTAs/SM

__device__ __forceinline__ void delta_load_stage(uint32_t st, const __nv_bfloat16* Eb,
                                                 const __nv_bfloat16* Xb, int kc, int tid) {
    #pragma unroll
    for (int i = 0; i < 8; i++) {
        int idx = tid + i * 128;
        int m = idx >> 3, ch = idx & 7;
        uint32_t dst = st + SWZ((uint32_t)(m * 128 + ch * 16));
        CP_ASYNC16(dst, Eb + (size_t)m * NN + kc + ch * 8);
    }
    #pragma unroll
    for (int i = 0; i < 4; i++) {
        int idx = tid + i * 128;
        int k = idx >> 3, ch = idx & 7;
        uint32_t dst = st + 16384 + SWZ((uint32_t)(k * 128 + ch * 16));
        CP_ASYNC16(dst, Xb + (size_t)(kc + k) * DD + ch * 8);
    }
}

__global__ __launch_bounds__(128, 3) void k_delta_mma(const float* __restrict__ x,
                                                      float* __restrict__ out) {
    extern __shared__ __align__(128) char smem[];
    uint32_t sb = smem_u32(smem);
    int tid = threadIdx.x;
    int lane = tid & 31, wid = tid >> 5;
    int warp_m = wid & 1, warp_n = wid >> 1;   // 2m x 2n, warp tile 64x32
    int b = blockIdx.z;
    int q0 = blockIdx.y * 128, d0 = blockIdx.x * 64;

    const __nv_bfloat16* Eb = g_Eb + (size_t)b * NN * NN + (size_t)q0 * NN;
    const __nv_bfloat16* Xb = g_xb + (size_t)b * NN * DD + d0;
    float acc[4][4][4] = {};
    const int DNC = NN / DK;   // 32

    delta_load_stage(sb, Eb, Xb, 0, tid);  CP_COMMIT();
    delta_load_stage(sb + DSTAGE, Eb, Xb, DK, tid);  CP_COMMIT();
    delta_load_stage(sb + 2 * DSTAGE, Eb, Xb, 2 * DK, tid);  CP_COMMIT();

    for (int c = 0; c < DNC; c++) {
        CP_WAIT2();
        __syncthreads();
        uint32_t stA = sb + (c % 3) * DSTAGE;
        uint32_t stB = stA + 16384;
        #pragma unroll
        for (int ks = 0; ks < 4; ks++) {
            uint32_t a[4][4];
            #pragma unroll
            for (int mt = 0; mt < 4; mt++) {
                int row = warp_m * 64 + mt * 16 + (lane & 15);
                uint32_t addr = stA + SWZ((uint32_t)(row * 128 + ks * 32 + (lane >> 4) * 16));
                LDSM_X4(a[mt], addr);
            }
            uint32_t bf[2][4];
            #pragma unroll
            for (int np = 0; np < 2; np++) {
                int k = ks * 16 + (lane & 15);
                int n = warp_n * 32 + np * 16 + (lane >> 4) * 8;
                uint32_t addr = stB + SWZ((uint32_t)(k * 128 + n * 2));
                LDSM_X4T(bf[np], addr);
            }
            #pragma unroll
            for (int mt = 0; mt < 4; mt++)
                #pragma unroll
                for (int nt = 0; nt < 4; nt++) {
                    int np = nt >> 1, o = (nt & 1) * 2;
                    MMA16816(acc[mt][nt], a[mt], bf[np][o], bf[np][o + 1]);
                }
        }
        __syncthreads();
        if (c + 3 < DNC) {
            delta_load_stage(sb + (c % 3) * DSTAGE, Eb, Xb, (c + 3) * DK, tid);
            CP_COMMIT();
        }
    }

    #pragma unroll
    for (int mt = 0; mt < 4; mt++) {
        int r0 = q0 + warp_m * 64 + mt * 16 + (lane >> 2);
        int r1 = r0 + 8;
        float l0 = g_L[b * NN + r0];
        float l1 = g_L[b * NN + r1];
        #pragma unroll
        for (int nt = 0; nt < 4; nt++) {
            int col = d0 + warp_n * 32 + nt * 8 + (lane & 3) * 2;
            size_t p0 = ((size_t)b * NN + r0) * DD + col;
            size_t p1 = ((size_t)b * NN + r1) * DD + col;
            float2 x0 = *(const float2*)&x[p0];
            float2 x1 = *(const float2*)&x[p1];
            *(float2*)&out[p0] = make_float2(fmaf(acc[mt][nt][0], l0, x0.x),
                                             fmaf(acc[mt][nt][1], l0, x0.y));
            *(float2*)&out[p1] = make_float2(fmaf(acc[mt][nt][2], l1, x1.x),
                                             fmaf(acc[mt][nt][3], l1, x1.y));
        }
    }
}

// ---------------- K6: in-place LayerNorm on out (float4) ----------------
__global__ __launch_bounds__(256) void k_ln(float* __restrict__ out,
                                            const float* __restrict__ gamma,
                                            const float* __restrict__ beta) {
    size_t row = blockIdx.x;
    float* y = out + row * DD;
    int tid = threadIdx.x;
    float4 v = *(float4*)&y[tid * 4];
    float mu = block_sum(v.x + v.y + v.z + v.w) * (1.0f / DD);
    float dx = v.x - mu, dy = v.y - mu, dz = v.z - mu, dw = v.w - mu;
    float var = block_sum(dx * dx + dy * dy + dz * dz + dw * dw) * (1.0f / DD);
    float inv = rsqrtf(var + LN_EPS);
    float4 g = *(const float4*)&gamma[tid * 4];
    float4 be = *(const float4*)&beta[tid * 4];
    float4 o;
    o.x = dx * inv * g.x + be.x;
    o.y = dy * inv * g.y + be.y;
    o.z = dz * inv * g.z + be.z;
    o.w = dw * inv * g.w + be.w;
    *(float4*)&y[tid * 4] = o;
}

extern "C" void kernel_launch(void* const* d_in, const int* in_sizes, int n_in,
                              void* d_out, int out_size) {
    const float* x     = (const float*)d_in[0];
    const float* mask  = (const float*)d_in[1];
    const float* U     = (const float*)d_in[2];
    const float* V     = (const float*)d_in[3];
    const float* gamma = (const float*)d_in[4];
    const float* beta  = (const float*)d_in[5];
    float* out = (float*)d_out;

    cudaFuncSetAttribute(k_proj_mma, cudaFuncAttributeMaxDynamicSharedMemorySize, PSMEM);
    cudaFuncSetAttribute(k_delta_mma, cudaFuncAttributeMaxDynamicSharedMemorySize, DSMEM);

    k_prep<<<XB_BLOCKS + RF_BLOCKS + WC_BLOCKS, 256>>>(x, mask, U, V);
    k_proj_mma<<<dim3(1, BB * NN / 64, 1), 256, PSMEM>>>(mask);
    dim3 gs(NN / 128, NN / 128, BB);
    k_scores_mma<<<gs, 256>>>();
    k_lred<<<BB * NN / 256, 256>>>();
    dim3 gd(DD / 64, NN / 128, BB);
    k_delta_mma<<<gd, 128, DSMEM>>>(x, out);
    k_ln<<<BB * NN, 256>>>(out, gamma, beta);
}

// round 14
// speedup vs baseline: 1.0919x; 1.0039x over previous
#include <cuda_runtime.h>
#include <cuda_bf16.h>
#include <math.h>
#include <stdint.h>

#define BB 4
#define NN 2048
#define DD 1024
#define RR 64
#define LN_EPS 1e-5f

// ---------------- scratch (device globals; allocation-free) ----------------
__device__ __align__(128) __nv_bfloat16 g_Qb[BB * NN * RR];          // 1 MB (mask & rs folded)
__device__ __align__(128) __nv_bfloat16 g_Kb[BB * NN * RR];          // 1 MB (mask folded)
__device__ __align__(128) __nv_bfloat16 g_Eb[(size_t)BB * NN * NN];  // 32 MB exp(s) bf16
__device__ __align__(128) __nv_bfloat16 g_xb[(size_t)BB * NN * DD];  // 16 MB x bf16
__device__ __align__(128) __nv_bfloat16 g_Wb[DD * 128];              // 256 KB [U|V] bf16
__device__ float g_Lp[16][BB * NN];                                  // partials, [nblk][token]
__device__ float g_rs[BB * NN];                                      // rsqrt(max(sum mask,1))

// ---------------- PTX helpers (sm_103 base ISA; no tcgen05) ----------------
__device__ __forceinline__ uint32_t smem_u32(const void* p) {
    uint32_t a;
    asm("{ .reg .u64 t; cvta.to.shared.u64 t, %1; cvt.u32.u64 %0, t; }" : "=r"(a) : "l"(p));
    return a;
}

#define LDSM_X4(r, a) \
    asm volatile("ldmatrix.sync.aligned.m8n8.x4.shared.b16 {%0,%1,%2,%3}, [%4];" \
        : "=r"((r)[0]), "=r"((r)[1]), "=r"((r)[2]), "=r"((r)[3]) : "r"(a))
#define LDSM_X4T(r, a) \
    asm volatile("ldmatrix.sync.aligned.m8n8.x4.trans.shared.b16 {%0,%1,%2,%3}, [%4];" \
        : "=r"((r)[0]), "=r"((r)[1]), "=r"((r)[2]), "=r"((r)[3]) : "r"(a))
#define MMA16816(c, a, b0, b1) \
    asm volatile("mma.sync.aligned.m16n8k16.row.col.f32.bf16.bf16.f32 " \
        "{%0,%1,%2,%3}, {%4,%5,%6,%7}, {%8,%9}, {%0,%1,%2,%3};" \
        : "+f"((c)[0]), "+f"((c)[1]), "+f"((c)[2]), "+f"((c)[3]) \
        : "r"((a)[0]), "r"((a)[1]), "r"((a)[2]), "r"((a)[3]), "r"(b0), "r"(b1))
#define CP_ASYNC16(dst, src) \
    asm volatile("cp.async.cg.shared.global [%0], [%1], 16;" :: "r"(dst), "l"(src))
#define CP_COMMIT() asm volatile("cp.async.commit_group;")
#define CP_WAIT2()  asm volatile("cp.async.wait_group 2;")

// SW128 swizzle for 128B rows (bits[4:6] ^= bits[7:9])
#define SWZ(off)  ((off) ^ (((off) >> 3) & 0x70))
// swizzle for 256B rows: 16B-chunk low-3 ^= k-row&7
#define BSWZ(off) ((off) ^ ((((off) >> 8) & 7) << 4))

// ---------------- block reductions ----------------
__device__ __forceinline__ float block_sum(float v) {
    __shared__ float red_s[8];
    #pragma unroll
    for (int o = 16; o; o >>= 1) v += __shfl_xor_sync(0xffffffffu, v, o);
    if ((threadIdx.x & 31) == 0) red_s[threadIdx.x >> 5] = v;
    __syncthreads();
    float r = 0.f;
    #pragma unroll
    for (int i = 0; i < 8; i++) r += red_s[i];
    __syncthreads();
    return r;
}

// ---------------- K0: fused preamble: x->bf16 | reff | [U|V]->bf16 ----------------
#define XB_BLOCKS (BB * NN * DD / 4 / 256)   // 8192
#define RF_BLOCKS (BB * NN / 8)              // 1024
#define WC_BLOCKS 128

__global__ __launch_bounds__(256) void k_prep(const float* __restrict__ x,
                                              const float* __restrict__ mask,
                                              const float* __restrict__ U,
                                              const float* __restrict__ V) {
    int bidx = blockIdx.x;
    if (bidx < XB_BLOCKS) {
        size_t i = (size_t)bidx * 256 + threadIdx.x;   // float4 index
        float4 v = *((const float4*)x + i);
        __nv_bfloat162* o = (__nv_bfloat162*)g_xb + i * 2;
        o[0] = __float22bfloat162_rn(make_float2(v.x, v.y));
        o[1] = __float22bfloat162_rn(make_float2(v.z, v.w));
    } else if (bidx < XB_BLOCKS + RF_BLOCKS) {
        int t = (bidx - XB_BLOCKS) * 8 + (threadIdx.x >> 5);
        int lane = threadIdx.x & 31;
        float v = mask[t * RR + lane] + mask[t * RR + 32 + lane];
        #pragma unroll
        for (int o = 16; o; o >>= 1) v += __shfl_xor_sync(0xffffffffu, v, o);
        if (lane == 0) g_rs[t] = rsqrtf(fmaxf(v, 1.0f));
    } else {
        int i = (bidx - XB_BLOCKS - RF_BLOCKS) * 256 + threadIdx.x;  // float4 slots
        int half = i >> 14;
        int j = i & 16383;
        int k = j >> 4, r4 = (j & 15) * 4;
        const float* src = half ? V : U;
        float4 v = *(const float4*)&src[k * RR + r4];
        __nv_bfloat162* o = (__nv_bfloat162*)&g_Wb[k * 128 + half * 64 + r4];
        o[0] = __float22bfloat162_rn(make_float2(v.x, v.y));
        o[1] = __float22bfloat162_rn(make_float2(v.z, v.w));
    }
}

// ---------------- K1: [Q|K] = x @ [U|V] (bf16 MMA), CTA 64x128, 8 warps 2m x 4n ----------------
#define PSTAGE 24576              // A 8KB (64x64) + B 16KB (64x128)
#define PSMEM (3 * PSTAGE)        // 72 KB

__device__ __forceinline__ void proj_load_stage(uint32_t st, const __nv_bfloat16* A,
                                                int kc, int tid) {
    #pragma unroll
    for (int i = 0; i < 2; i++) {
        int idx = tid + i * 256;
        int m = idx >> 3, ch = idx & 7;
        uint32_t dst = st + SWZ((uint32_t)(m * 128 + ch * 16));
        CP_ASYNC16(dst, A + (size_t)m * DD + kc + ch * 8);
    }
    #pragma unroll
    for (int i = 0; i < 4; i++) {
        int idx = tid + i * 256;
        int k = idx >> 4, ch = idx & 15;
        uint32_t dst = st + 8192 + BSWZ((uint32_t)(k * 256 + ch * 16));
        CP_ASYNC16(dst, g_Wb + (size_t)(kc + k) * 128 + ch * 8);
    }
}

__global__ __launch_bounds__(256) void k_proj_mma(const float* __restrict__ mask) {
    extern __shared__ __align__(128) char smem[];
    uint32_t sb = smem_u32(smem);
    int tid = threadIdx.x;
    int lane = tid & 31, wid = tid >> 5;
    int warp_m = wid & 1, warp_n = wid >> 1;
    int m0 = blockIdx.y * 64;

    const __nv_bfloat16* A = g_xb + (size_t)m0 * DD;
    float acc[2][4][4] = {};
    const int PNC = DD / 64;   // 16

    proj_load_stage(sb, A, 0, tid);  CP_COMMIT();
    proj_load_stage(sb + PSTAGE, A, 64, tid);  CP_COMMIT();
    proj_load_stage(sb + 2 * PSTAGE, A, 128, tid);  CP_COMMIT();

    for (int c = 0; c < PNC; c++) {
        CP_WAIT2();
        __syncthreads();
        uint32_t stA = sb + (c % 3) * PSTAGE;
        uint32_t stB = stA + 8192;
        #pragma unroll
        for (int ks = 0; ks < 4; ks++) {
            uint32_t a[2][4];
            #pragma unroll
            for (int mt = 0; mt < 2; mt++) {
                int row = warp_m * 32 + mt * 16 + (lane & 15);
                uint32_t addr = stA + SWZ((uint32_t)(row * 128 + ks * 32 + (lane >> 4) * 16));
                LDSM_X4(a[mt], addr);
            }
            uint32_t bf[2][4];
            #pragma unroll
            for (int np = 0; np < 2; np++) {
                int k = ks * 16 + (lane & 15);
                int n = warp_n * 32 + np * 16 + (lane >> 4) * 8;
                uint32_t addr = stB + BSWZ((uint32_t)(k * 256 + n * 2));
                LDSM_X4T(bf[np], addr);
            }
            #pragma unroll
            for (int mt = 0; mt < 2; mt++)
                #pragma unroll
                for (int nt = 0; nt < 4; nt++) {
                    int np = nt >> 1, o = (nt & 1) * 2;
                    MMA16816(acc[mt][nt], a[mt], bf[np][o], bf[np][o + 1]);
                }
        }
        __syncthreads();
        if (c + 3 < PNC) {
            proj_load_stage(sb + (c % 3) * PSTAGE, A, (c + 3) * 64, tid);
            CP_COMMIT();
        }
    }

    #pragma unroll
    for (int mt = 0; mt < 2; mt++) {
        int t0 = m0 + warp_m * 32 + mt * 16 + (lane >> 2);
        int t1 = t0 + 8;
        float rs0 = g_rs[t0], rs1 = g_rs[t1];
        #pragma unroll
        for (int nt = 0; nt < 4; nt++) {
            int c = warp_n * 32 + nt * 8 + (lane & 3) * 2;
            if (c < 64) {
                float2 mk0 = *(const float2*)&mask[(size_t)t0 * RR + c];
                float2 mk1 = *(const float2*)&mask[(size_t)t1 * RR + c];
                *(__nv_bfloat162*)&g_Qb[(size_t)t0 * RR + c] = __float22bfloat162_rn(
                    make_float2(acc[mt][nt][0] * mk0.x * rs0, acc[mt][nt][1] * mk0.y * rs0));
                *(__nv_bfloat162*)&g_Qb[(size_t)t1 * RR + c] = __float22bfloat162_rn(
                    make_float2(acc[mt][nt][2] * mk1.x * rs1, acc[mt][nt][3] * mk1.y * rs1));
            } else {
                int c2 = c - 64;
                float2 mk0 = *(const float2*)&mask[(size_t)t0 * RR + c2];
                float2 mk1 = *(const float2*)&mask[(size_t)t1 * RR + c2];
                *(__nv_bfloat162*)&g_Kb[(size_t)t0 * RR + c2] = __float22bfloat162_rn(
                    make_float2(acc[mt][nt][0] * mk0.x, acc[mt][nt][1] * mk0.y));
                *(__nv_bfloat162*)&g_Kb[(size_t)t1 * RR + c2] = __float22bfloat162_rn(
                    make_float2(acc[mt][nt][2] * mk1.x, acc[mt][nt][3] * mk1.y));
            }
        }
    }
}

// ---------------- K2: E = exp(Q @ K^T), coalesced partial row sums ----------------
__global__ __launch_bounds__(256) void k_scores_mma() {
    __shared__ __align__(128) char smem[32768];   // A 16KB + B 16KB
    __shared__ float ssum[4][128];
    uint32_t sb = smem_u32(smem);
    int tid = threadIdx.x;
    int lane = tid & 31, wid = tid >> 5;
    int warp_m = wid & 1, warp_n = wid >> 1;
    int b = blockIdx.z;
    int q0 = blockIdx.y * 128, n0 = blockIdx.x * 128;

    const __nv_bfloat16* Qb = g_Qb + ((size_t)b * NN + q0) * RR;
    const __nv_bfloat16* Kb = g_Kb + ((size_t)b * NN + n0) * RR;
    uint32_t sA = sb, sB = sb + 16384;

    #pragma unroll
    for (int i = 0; i < 4; i++) {
        int idx = tid + i * 256;
        int row = idx >> 3, ch = idx & 7;
        uint4 v = *(const uint4*)&Qb[row * RR + ch * 8];
        uint32_t off = SWZ((uint32_t)(row * 128 + ch * 16));
        asm volatile("st.shared.v4.b32 [%0], {%1,%2,%3,%4};"
                     :: "r"(sA + off), "r"(v.x), "r"(v.y), "r"(v.z), "r"(v.w) : "memory");
        uint4 w = *(const uint4*)&Kb[row * RR + ch * 8];
        asm volatile("st.shared.v4.b32 [%0], {%1,%2,%3,%4};"
                     :: "r"(sB + off), "r"(w.x), "r"(w.y), "r"(w.z), "r"(w.w) : "memory");
    }
    __syncthreads();

    float acc[4][4][4] = {};
    #pragma unroll
    for (int ks = 0; ks < 4; ks++) {
        uint32_t a[4][4];
        #pragma unroll
        for (int mt = 0; mt < 4; mt++) {
            int row = warp_m * 64 + mt * 16 + (lane & 15);
            uint32_t addr = sA + SWZ((uint32_t)(row * 128 + ks * 32 + (lane >> 4) * 16));
            LDSM_X4(a[mt], addr);
        }
        uint32_t bf[2][4];
        #pragma unroll
        for (int np = 0; np < 2; np++) {
            int row = warp_n * 32 + np * 16 + (lane & 15);
            uint32_t addr = sB + SWZ((uint32_t)(row * 128 + ks * 32 + (lane >> 4) * 16));
            LDSM_X4(bf[np], addr);
        }
        #pragma unroll
        for (int mt = 0; mt < 4; mt++)
            #pragma unroll
            for (int nt = 0; nt < 4; nt++) {
                int np = nt >> 1, o = nt & 1;
                MMA16816(acc[mt][nt], a[mt], bf[np][o], bf[np][o + 2]);
            }
    }

    __nv_bfloat16* Eb = g_Eb + (size_t)b * NN * NN;
    #pragma unroll
    for (int mt = 0; mt < 4; mt++) {
        int r0 = warp_m * 64 + mt * 16 + (lane >> 2);
        int r1 = r0 + 8;
        float s0 = 0.f, s1 = 0.f;
        #pragma unroll
        for (int nt = 0; nt < 4; nt++) {
            int col = n0 + warp_n * 32 + nt * 8 + (lane & 3) * 2;
            float e0 = __expf(acc[mt][nt][0]);
            float e1 = __expf(acc[mt][nt][1]);
            float e2 = __expf(acc[mt][nt][2]);
            float e3 = __expf(acc[mt][nt][3]);
            s0 += e0 + e1; s1 += e2 + e3;
            *(__nv_bfloat162*)&Eb[(size_t)(q0 + r0) * NN + col] =
                __float22bfloat162_rn(make_float2(e0, e1));
            *(__nv_bfloat162*)&Eb[(size_t)(q0 + r1) * NN + col] =
                __float22bfloat162_rn(make_float2(e2, e3));
        }
        s0 += __shfl_xor_sync(0xffffffffu, s0, 1);
        s0 += __shfl_xor_sync(0xffffffffu, s0, 2);
        s1 += __shfl_xor_sync(0xffffffffu, s1, 1);
        s1 += __shfl_xor_sync(0xffffffffu, s1, 2);
        if ((lane & 3) == 0) {
            ssum[warp_n][r0] = s0;
            ssum[warp_n][r1] = s1;
        }
    }
    __syncthreads();
    if (tid < 128) {
        float s = ssum[0][tid] + ssum[1][tid] + ssum[2][tid] + ssum[3][tid];
        g_Lp[blockIdx.x][(size_t)b * NN + q0 + tid] = s;   // coalesced: [nblk][token]
    }
}

// ---------------- K4: out = x + (E @ xb)*(1/l), CTA 128x64, 4 warps 2m x 2n (64x32) ----------------
// L-reduction fused into prologue: each CTA computes 1/rowsum for its 128 q rows.
#define DK 64
#define DSTAGE 24576              // A 16KB (128x64) + B 8KB (64x64)
#define DSMEM (3 * DSTAGE)        // 72 KB -> 3 CTAs/SM

__device__ __forceinline__ void delta_load_stage(uint32_t st, const __nv_bfloat16* Eb,
                                                 const __nv_bfloat16* Xb, int kc, int tid) {
    #pragma unroll
    for (int i = 0; i < 8; i++) {
        int idx = tid + i * 128;
        int m = idx >> 3, ch = idx & 7;
        uint32_t dst = st + SWZ((uint32_t)(m * 128 + ch * 16));
        CP_ASYNC16(dst, Eb + (size_t)m * NN + kc + ch * 8);
    }
    #pragma unroll
    for (int i = 0; i < 4; i++) {
        int idx = tid + i * 128;
        int k = idx >> 3, ch = idx & 7;
        uint32_t dst = st + 16384 + SWZ((uint32_t)(k * 128 + ch * 16));
        CP_ASYNC16(dst, Xb + (size_t)(kc + k) * DD + ch * 8);
    }
}

__global__ __launch_bounds__(128, 3) void k_delta_mma(const float* __restrict__ x,
                                                      float* __restrict__ out) {
    extern __shared__ __align__(128) char smem[];
    __shared__ float sL[128];
    uint32_t sb = smem_u32(smem);
    int tid = threadIdx.x;
    int lane = tid & 31, wid = tid >> 5;
    int warp_m = wid & 1, warp_n = wid >> 1;   // 2m x 2n, warp tile 64x32
    int b = blockIdx.z;
    int q0 = blockIdx.y * 128, d0 = blockIdx.x * 64;

    const __nv_bfloat16* Eb = g_Eb + (size_t)b * NN * NN + (size_t)q0 * NN;
    const __nv_bfloat16* Xb = g_xb + (size_t)b * NN * DD + d0;
    float acc[4][4][4] = {};
    const int DNC = NN / DK;   // 32

    delta_load_stage(sb, Eb, Xb, 0, tid);  CP_COMMIT();
    delta_load_stage(sb + DSTAGE, Eb, Xb, DK, tid);  CP_COMMIT();
    delta_load_stage(sb + 2 * DSTAGE, Eb, Xb, 2 * DK, tid);  CP_COMMIT();

    // fused L-reduction for this CTA's q band (overlaps with stage loads;
    // ordered before epilogue by the mainloop's __syncthreads)
    {
        int t = b * NN + q0 + tid;
        float s = 0.f;
        #pragma unroll
        for (int i = 0; i < 16; i++) s += g_Lp[i][t];
        sL[tid] = 1.0f / s;
    }

    for (int c = 0; c < DNC; c++) {
        CP_WAIT2();
        __syncthreads();
        uint32_t stA = sb + (c % 3) * DSTAGE;
        uint32_t stB = stA + 16384;
        #pragma unroll
        for (int ks = 0; ks < 4; ks++) {
            uint32_t a[4][4];
            #pragma unroll
            for (int mt = 0; mt < 4; mt++) {
                int row = warp_m * 64 + mt * 16 + (lane & 15);
                uint32_t addr = stA + SWZ((uint32_t)(row * 128 + ks * 32 + (lane >> 4) * 16));
                LDSM_X4(a[mt], addr);
            }
            uint32_t bf[2][4];
            #pragma unroll
            for (int np = 0; np < 2; np++) {
                int k = ks * 16 + (lane & 15);
                int n = warp_n * 32 + np * 16 + (lane >> 4) * 8;
                uint32_t addr = stB + SWZ((uint32_t)(k * 128 + n * 2));
                LDSM_X4T(bf[np], addr);
            }
            #pragma unroll
            for (int mt = 0; mt < 4; mt++)
                #pragma unroll
                for (int nt = 0; nt < 4; nt++) {
                    int np = nt >> 1, o = (nt & 1) * 2;
                    MMA16816(acc[mt][nt], a[mt], bf[np][o], bf[np][o + 1]);
                }
        }
        __syncthreads();
        if (c + 3 < DNC) {
            delta_load_stage(sb + (c % 3) * DSTAGE, Eb, Xb, (c + 3) * DK, tid);
            CP_COMMIT();
        }
    }

    #pragma unroll
    for (int mt = 0; mt < 4; mt++) {
        int rr0 = warp_m * 64 + mt * 16 + (lane >> 2);
        int rr1 = rr0 + 8;
        int r0 = q0 + rr0, r1 = q0 + rr1;
        float l0 = sL[rr0];
        float l1 = sL[rr1];
        #pragma unroll
        for (int nt = 0; nt < 4; nt++) {
            int col = d0 + warp_n * 32 + nt * 8 + (lane & 3) * 2;
            size_t p0 = ((size_t)b * NN + r0) * DD + col;
            size_t p1 = ((size_t)b * NN + r1) * DD + col;
            float2 x0 = *(const float2*)&x[p0];
            float2 x1 = *(const float2*)&x[p1];
            *(float2*)&out[p0] = make_float2(fmaf(acc[mt][nt][0], l0, x0.x),
                                             fmaf(acc[mt][nt][1], l0, x0.y));
            *(float2*)&out[p1] = make_float2(fmaf(acc[mt][nt][2], l1, x1.x),
                                             fmaf(acc[mt][nt][3], l1, x1.y));
        }
    }
}

// ---------------- K6: in-place LayerNorm on out (float4) ----------------
__global__ __launch_bounds__(256) void k_ln(float* __restrict__ out,
                                            const float* __restrict__ gamma,
                                            const float* __restrict__ beta) {
    size_t row = blockIdx.x;
    float* y = out + row * DD;
    int tid = threadIdx.x;
    float4 v = *(float4*)&y[tid * 4];
    float mu = block_sum(v.x + v.y + v.z + v.w) * (1.0f / DD);
    float dx = v.x - mu, dy = v.y - mu, dz = v.z - mu, dw = v.w - mu;
    float var = block_sum(dx * dx + dy * dy + dz * dz + dw * dw) * (1.0f / DD);
    float inv = rsqrtf(var + LN_EPS);
    float4 g = *(const float4*)&gamma[tid * 4];
    float4 be = *(const float4*)&beta[tid * 4];
    float4 o;
    o.x = dx * inv * g.x + be.x;
    o.y = dy * inv * g.y + be.y;
    o.z = dz * inv * g.z + be.z;
    o.w = dw * inv * g.w + be.w;
    *(float4*)&y[tid * 4] = o;
}

extern "C" void kernel_launch(void* const* d_in, const int* in_sizes, int n_in,
                              void* d_out, int out_size) {
    const float* x     = (const float*)d_in[0];
    const float* mask  = (const float*)d_in[1];
    const float* U     = (const float*)d_in[2];
    const float* V     = (const float*)d_in[3];
    const float* gamma = (const float*)d_in[4];
    const float* beta  = (const float*)d_in[5];
    float* out = (float*)d_out;

    cudaFuncSetAttribute(k_proj_mma, cudaFuncAttributeMaxDynamicSharedMemorySize, PSMEM);
    cudaFuncSetAttribute(k_delta_mma, cudaFuncAttributeMaxDynamicSharedMemorySize, DSMEM);

    k_prep<<<XB_BLOCKS + RF_BLOCKS + WC_BLOCKS, 256>>>(x, mask, U, V);
    k_proj_mma<<<dim3(1, BB * NN / 64, 1), 256, PSMEM>>>(mask);
    dim3 gs(NN / 128, NN / 128, BB);
    k_scores_mma<<<gs, 256>>>();
    dim3 gd(DD / 64, NN / 128, BB);
    k_delta_mma<<<gd, 128, DSMEM>>>(x, out);
    k_ln<<<BB * NN, 256>>>(out, gamma, beta);
}

// round 16
// speedup vs baseline: 1.1275x; 1.0326x over previous
#include <cuda_runtime.h>
#include <cuda_bf16.h>
#include <math.h>
#include <stdint.h>

#define BB 4
#define NN 2048
#define DD 1024
#define RR 64
#define LN_EPS 1e-5f

// ---------------- scratch (device globals; allocation-free) ----------------
__device__ __align__(128) __nv_bfloat16 g_Qb[BB * NN * RR];          // 1 MB (mask & rs folded)
__device__ __align__(128) __nv_bfloat16 g_Kb[BB * NN * RR];          // 1 MB (mask folded)
__device__ __align__(128) __nv_bfloat16 g_Eb[(size_t)BB * NN * NN];  // 32 MB exp(s) bf16
__device__ __align__(128) __nv_bfloat16 g_xb[(size_t)BB * NN * DD];  // 16 MB x bf16
__device__ __align__(128) __nv_bfloat16 g_Wb[DD * 128];              // 256 KB [U|V] bf16
__device__ float g_Lp[16][BB * NN];                                  // partials, [nblk][token]
__device__ float g_rs[BB * NN];                                      // rsqrt(max(sum mask,1))

// ---------------- PTX helpers (sm_103 base ISA; no tcgen05) ----------------
__device__ __forceinline__ uint32_t smem_u32(const void* p) {
    uint32_t a;
    asm("{ .reg .u64 t; cvta.to.shared.u64 t, %1; cvt.u32.u64 %0, t; }" : "=r"(a) : "l"(p));
    return a;
}

#define LDSM_X4(r, a) \
    asm volatile("ldmatrix.sync.aligned.m8n8.x4.shared.b16 {%0,%1,%2,%3}, [%4];" \
        : "=r"((r)[0]), "=r"((r)[1]), "=r"((r)[2]), "=r"((r)[3]) : "r"(a))
#define LDSM_X4T(r, a) \
    asm volatile("ldmatrix.sync.aligned.m8n8.x4.trans.shared.b16 {%0,%1,%2,%3}, [%4];" \
        : "=r"((r)[0]), "=r"((r)[1]), "=r"((r)[2]), "=r"((r)[3]) : "r"(a))
#define MMA16816(c, a, b0, b1) \
    asm volatile("mma.sync.aligned.m16n8k16.row.col.f32.bf16.bf16.f32 " \
        "{%0,%1,%2,%3}, {%4,%5,%6,%7}, {%8,%9}, {%0,%1,%2,%3};" \
        : "+f"((c)[0]), "+f"((c)[1]), "+f"((c)[2]), "+f"((c)[3]) \
        : "r"((a)[0]), "r"((a)[1]), "r"((a)[2]), "r"((a)[3]), "r"(b0), "r"(b1))
#define CP_ASYNC16(dst, src) \
    asm volatile("cp.async.cg.shared.global [%0], [%1], 16;" :: "r"(dst), "l"(src))
#define CP_COMMIT() asm volatile("cp.async.commit_group;")
#define CP_WAIT2()  asm volatile("cp.async.wait_group 2;")
#define CP_WAIT1()  asm volatile("cp.async.wait_group 1;")
#define CP_WAIT0()  asm volatile("cp.async.wait_group 0;")

// SW128 swizzle for 128B rows (bits[4:6] ^= bits[7:9])
#define SWZ(off)  ((off) ^ (((off) >> 3) & 0x70))
// swizzle for 256B rows: 16B-chunk low-3 ^= k-row&7
#define BSWZ(off) ((off) ^ ((((off) >> 8) & 7) << 4))

// ---------------- block reductions ----------------
__device__ __forceinline__ float block_sum(float v) {
    __shared__ float red_s[8];
    #pragma unroll
    for (int o = 16; o; o >>= 1) v += __shfl_xor_sync(0xffffffffu, v, o);
    if ((threadIdx.x & 31) == 0) red_s[threadIdx.x >> 5] = v;
    __syncthreads();
    float r = 0.f;
    #pragma unroll
    for (int i = 0; i < 8; i++) r += red_s[i];
    __syncthreads();
    return r;
}

// ---------------- K0: fused preamble: x->bf16 | reff | [U|V]->bf16 ----------------
#define XB_BLOCKS (BB * NN * DD / 4 / 256)   // 8192
#define RF_BLOCKS (BB * NN / 8)              // 1024
#define WC_BLOCKS 128

__global__ __launch_bounds__(256) void k_prep(const float* __restrict__ x,
                                              const float* __restrict__ mask,
                                              const float* __restrict__ U,
                                              const float* __restrict__ V) {
    int bidx = blockIdx.x;
    if (bidx < XB_BLOCKS) {
        size_t i = (size_t)bidx * 256 + threadIdx.x;   // float4 index
        float4 v = *((const float4*)x + i);
        __nv_bfloat162* o = (__nv_bfloat162*)g_xb + i * 2;
        o[0] = __float22bfloat162_rn(make_float2(v.x, v.y));
        o[1] = __float22bfloat162_rn(make_float2(v.z, v.w));
    } else if (bidx < XB_BLOCKS + RF_BLOCKS) {
        int t = (bidx - XB_BLOCKS) * 8 + (threadIdx.x >> 5);
        int lane = threadIdx.x & 31;
        float v = mask[t * RR + lane] + mask[t * RR + 32 + lane];
        #pragma unroll
        for (int o = 16; o; o >>= 1) v += __shfl_xor_sync(0xffffffffu, v, o);
        if (lane == 0) g_rs[t] = rsqrtf(fmaxf(v, 1.0f));
    } else {
        int i = (bidx - XB_BLOCKS - RF_BLOCKS) * 256 + threadIdx.x;  // float4 slots
        int half = i >> 14;
        int j = i & 16383;
        int k = j >> 4, r4 = (j & 15) * 4;
        const float* src = half ? V : U;
        float4 v = *(const float4*)&src[k * RR + r4];
        __nv_bfloat162* o = (__nv_bfloat162*)&g_Wb[k * 128 + half * 64 + r4];
        o[0] = __float22bfloat162_rn(make_float2(v.x, v.y));
        o[1] = __float22bfloat162_rn(make_float2(v.z, v.w));
    }
}

// ---------------- K1: [Q|K] = x @ [U|V] (bf16 MMA), CTA 64x128, 8 warps 2m x 4n ----------------
#define PSTAGE 24576              // A 8KB (64x64) + B 16KB (64x128)
#define PSMEM (3 * PSTAGE)        // 72 KB

__device__ __forceinline__ void proj_load_stage(uint32_t st, const __nv_bfloat16* A,
                                                int kc, int tid) {
    #pragma unroll
    for (int i = 0; i < 2; i++) {
        int idx = tid + i * 256;
        int m = idx >> 3, ch = idx & 7;
        uint32_t dst = st + SWZ((uint32_t)(m * 128 + ch * 16));
        CP_ASYNC16(dst, A + (size_t)m * DD + kc + ch * 8);
    }
    #pragma unroll
    for (int i = 0; i < 4; i++) {
        int idx = tid + i * 256;
        int k = idx >> 4, ch = idx & 15;
        uint32_t dst = st + 8192 + BSWZ((uint32_t)(k * 256 + ch * 16));
        CP_ASYNC16(dst, g_Wb + (size_t)(kc + k) * 128 + ch * 8);
    }
}

__global__ __launch_bounds__(256) void k_proj_mma(const float* __restrict__ mask) {
    extern __shared__ __align__(128) char smem[];
    uint32_t sb = smem_u32(smem);
    int tid = threadIdx.x;
    int lane = tid & 31, wid = tid >> 5;
    int warp_m = wid & 1, warp_n = wid >> 1;
    int m0 = blockIdx.y * 64;

    const __nv_bfloat16* A = g_xb + (size_t)m0 * DD;
    float acc[2][4][4] = {};
    const int PNC = DD / 64;   // 16

    proj_load_stage(sb, A, 0, tid);  CP_COMMIT();
    proj_load_stage(sb + PSTAGE, A, 64, tid);  CP_COMMIT();
    proj_load_stage(sb + 2 * PSTAGE, A, 128, tid);  CP_COMMIT();

    for (int c = 0; c < PNC; c++) {
        CP_WAIT2();
        __syncthreads();
        uint32_t stA = sb + (c % 3) * PSTAGE;
        uint32_t stB = stA + 8192;
        #pragma unroll
        for (int ks = 0; ks < 4; ks++) {
            uint32_t a[2][4];
            #pragma unroll
            for (int mt = 0; mt < 2; mt++) {
                int row = warp_m * 32 + mt * 16 + (lane & 15);
                uint32_t addr = stA + SWZ((uint32_t)(row * 128 + ks * 32 + (lane >> 4) * 16));
                LDSM_X4(a[mt], addr);
            }
            uint32_t bf[2][4];
            #pragma unroll
            for (int np = 0; np < 2; np++) {
                int k = ks * 16 + (lane & 15);
                int n = warp_n * 32 + np * 16 + (lane >> 4) * 8;
                uint32_t addr = stB + BSWZ((uint32_t)(k * 256 + n * 2));
                LDSM_X4T(bf[np], addr);
            }
            #pragma unroll
            for (int mt = 0; mt < 2; mt++)
                #pragma unroll
                for (int nt = 0; nt < 4; nt++) {
                    int np = nt >> 1, o = (nt & 1) * 2;
                    MMA16816(acc[mt][nt], a[mt], bf[np][o], bf[np][o + 1]);
                }
        }
        __syncthreads();
        if (c + 3 < PNC) {
            proj_load_stage(sb + (c % 3) * PSTAGE, A, (c + 3) * 64, tid);
            CP_COMMIT();
        }
    }

    #pragma unroll
    for (int mt = 0; mt < 2; mt++) {
        int t0 = m0 + warp_m * 32 + mt * 16 + (lane >> 2);
        int t1 = t0 + 8;
        float rs0 = g_rs[t0], rs1 = g_rs[t1];
        #pragma unroll
        for (int nt = 0; nt < 4; nt++) {
            int c = warp_n * 32 + nt * 8 + (lane & 3) * 2;
            if (c < 64) {
                float2 mk0 = *(const float2*)&mask[(size_t)t0 * RR + c];
                float2 mk1 = *(const float2*)&mask[(size_t)t1 * RR + c];
                *(__nv_bfloat162*)&g_Qb[(size_t)t0 * RR + c] = __float22bfloat162_rn(
                    make_float2(acc[mt][nt][0] * mk0.x * rs0, acc[mt][nt][1] * mk0.y * rs0));
                *(__nv_bfloat162*)&g_Qb[(size_t)t1 * RR + c] = __float22bfloat162_rn(
                    make_float2(acc[mt][nt][2] * mk1.x * rs1, acc[mt][nt][3] * mk1.y * rs1));
            } else {
                int c2 = c - 64;
                float2 mk0 = *(const float2*)&mask[(size_t)t0 * RR + c2];
                float2 mk1 = *(const float2*)&mask[(size_t)t1 * RR + c2];
                *(__nv_bfloat162*)&g_Kb[(size_t)t0 * RR + c2] = __float22bfloat162_rn(
                    make_float2(acc[mt][nt][0] * mk0.x, acc[mt][nt][1] * mk0.y));
                *(__nv_bfloat162*)&g_Kb[(size_t)t1 * RR + c2] = __float22bfloat162_rn(
                    make_float2(acc[mt][nt][2] * mk1.x, acc[mt][nt][3] * mk1.y));
            }
        }
    }
}

// ---------------- K2: E = exp(Q @ K^T), coalesced partial row sums ----------------
__global__ __launch_bounds__(256) void k_scores_mma() {
    __shared__ __align__(128) char smem[32768];   // A 16KB + B 16KB
    __shared__ float ssum[4][128];
    uint32_t sb = smem_u32(smem);
    int tid = threadIdx.x;
    int lane = tid & 31, wid = tid >> 5;
    int warp_m = wid & 1, warp_n = wid >> 1;
    int b = blockIdx.z;
    int q0 = blockIdx.y * 128, n0 = blockIdx.x * 128;

    const __nv_bfloat16* Qb = g_Qb + ((size_t)b * NN + q0) * RR;
    const __nv_bfloat16* Kb = g_Kb + ((size_t)b * NN + n0) * RR;
    uint32_t sA = sb, sB = sb + 16384;

    #pragma unroll
    for (int i = 0; i < 4; i++) {
        int idx = tid + i * 256;
        int row = idx >> 3, ch = idx & 7;
        uint4 v = *(const uint4*)&Qb[row * RR + ch * 8];
        uint32_t off = SWZ((uint32_t)(row * 128 + ch * 16));
        asm volatile("st.shared.v4.b32 [%0], {%1,%2,%3,%4};"
                     :: "r"(sA + off), "r"(v.x), "r"(v.y), "r"(v.z), "r"(v.w) : "memory");
        uint4 w = *(const uint4*)&Kb[row * RR + ch * 8];
        asm volatile("st.shared.v4.b32 [%0], {%1,%2,%3,%4};"
                     :: "r"(sB + off), "r"(w.x), "r"(w.y), "r"(w.z), "r"(w.w) : "memory");
    }
    __syncthreads();

    float acc[4][4][4] = {};
    #pragma unroll
    for (int ks = 0; ks < 4; ks++) {
        uint32_t a[4][4];
        #pragma unroll
        for (int mt = 0; mt < 4; mt++) {
            int row = warp_m * 64 + mt * 16 + (lane & 15);
            uint32_t addr = sA + SWZ((uint32_t)(row * 128 + ks * 32 + (lane >> 4) * 16));
            LDSM_X4(a[mt], addr);
        }
        uint32_t bf[2][4];
        #pragma unroll
        for (int np = 0; np < 2; np++) {
            int row = warp_n * 32 + np * 16 + (lane & 15);
            uint32_t addr = sB + SWZ((uint32_t)(row * 128 + ks * 32 + (lane >> 4) * 16));
            LDSM_X4(bf[np], addr);
        }
        #pragma unroll
        for (int mt = 0; mt < 4; mt++)
            #pragma unroll
            for (int nt = 0; nt < 4; nt++) {
                int np = nt >> 1, o = nt & 1;
                MMA16816(acc[mt][nt], a[mt], bf[np][o], bf[np][o + 2]);
            }
    }

    __nv_bfloat16* Eb = g_Eb + (size_t)b * NN * NN;
    #pragma unroll
    for (int mt = 0; mt < 4; mt++) {
        int r0 = warp_m * 64 + mt * 16 + (lane >> 2);
        int r1 = r0 + 8;
        float s0 = 0.f, s1 = 0.f;
        #pragma unroll
        for (int nt = 0; nt < 4; nt++) {
            int col = n0 + warp_n * 32 + nt * 8 + (lane & 3) * 2;
            float e0 = __expf(acc[mt][nt][0]);
            float e1 = __expf(acc[mt][nt][1]);
            float e2 = __expf(acc[mt][nt][2]);
            float e3 = __expf(acc[mt][nt][3]);
            s0 += e0 + e1; s1 += e2 + e3;
            *(__nv_bfloat162*)&Eb[(size_t)(q0 + r0) * NN + col] =
                __float22bfloat162_rn(make_float2(e0, e1));
            *(__nv_bfloat162*)&Eb[(size_t)(q0 + r1) * NN + col] =
                __float22bfloat162_rn(make_float2(e2, e3));
        }
        s0 += __shfl_xor_sync(0xffffffffu, s0, 1);
        s0 += __shfl_xor_sync(0xffffffffu, s0, 2);
        s1 += __shfl_xor_sync(0xffffffffu, s1, 1);
        s1 += __shfl_xor_sync(0xffffffffu, s1, 2);
        if ((lane & 3) == 0) {
            ssum[warp_n][r0] = s0;
            ssum[warp_n][r1] = s1;
        }
    }
    __syncthreads();
    if (tid < 128) {
        float s = ssum[0][tid] + ssum[1][tid] + ssum[2][tid] + ssum[3][tid];
        g_Lp[blockIdx.x][(size_t)b * NN + q0 + tid] = s;   // coalesced: [nblk][token]
    }
}

// ---------------- K4: out = x + (E @ xb)*(1/l), CTA 128x64, 4 warps 2m x 2n (64x32) ----------------
// 2-stage double buffer, 4 CTAs/SM. L-reduction fused into prologue.
#define DK 64
#define DSTAGE 24576              // A 16KB (128x64) + B 8KB (64x64)
#define DSMEM (2 * DSTAGE)        // 48 KB -> 4 CTAs/SM

__device__ __forceinline__ void delta_load_stage(uint32_t st, const __nv_bfloat16* Eb,
                                                 const __nv_bfloat16* Xb, int kc, int tid) {
    #pragma unroll
    for (int i = 0; i < 8; i++) {
        int idx = tid + i * 128;
        int m = idx >> 3, ch = idx & 7;
        uint32_t dst = st + SWZ((uint32_t)(m * 128 + ch * 16));
        CP_ASYNC16(dst, Eb + (size_t)m * NN + kc + ch * 8);
    }
    #pragma unroll
    for (int i = 0; i < 4; i++) {
        int idx = tid + i * 128;
        int k = idx >> 3, ch = idx & 7;
        uint32_t dst = st + 16384 + SWZ((uint32_t)(k * 128 + ch * 16));
        CP_ASYNC16(dst, Xb + (size_t)(kc + k) * DD + ch * 8);
    }
}

__global__ __launch_bounds__(128, 4) void k_delta_mma(const float* __restrict__ x,
                                                      float* __restrict__ out) {
    extern __shared__ __align__(128) char smem[];
    __shared__ float sL[128];
    uint32_t sb = smem_u32(smem);
    int tid = threadIdx.x;
    int lane = tid & 31, wid = tid >> 5;
    int warp_m = wid & 1, warp_n = wid >> 1;   // 2m x 2n, warp tile 64x32
    int b = blockIdx.z;
    int q0 = blockIdx.y * 128, d0 = blockIdx.x * 64;

    const __nv_bfloat16* Eb = g_Eb + (size_t)b * NN * NN + (size_t)q0 * NN;
    const __nv_bfloat16* Xb = g_xb + (size_t)b * NN * DD + d0;
    float acc[4][4][4] = {};
    const int DNC = NN / DK;   // 32

    delta_load_stage(sb, Eb, Xb, 0, tid);  CP_COMMIT();

    // fused L-reduction for this CTA's q band (overlaps with stage-0 loads;
    // ordered before epilogue by the mainloop's __syncthreads)
    {
        int t = b * NN + q0 + tid;
        float s = 0.f;
        #pragma unroll
        for (int i = 0; i < 16; i++) s += g_Lp[i][t];
        sL[tid] = 1.0f / s;
    }

    for (int c = 0; c < DNC; c++) {
        if (c + 1 < DNC) {
            delta_load_stage(sb + ((c + 1) & 1) * DSTAGE, Eb, Xb, (c + 1) * DK, tid);
            CP_COMMIT();
            CP_WAIT1();
        } else {
            CP_WAIT0();
        }
        __syncthreads();
        uint32_t stA = sb + (c & 1) * DSTAGE;
        uint32_t stB = stA + 16384;
        #pragma unroll
        for (int ks = 0; ks < 4; ks++) {
            uint32_t a[4][4];
            #pragma unroll
            for (int mt = 0; mt < 4; mt++) {
                int row = warp_m * 64 + mt * 16 + (lane & 15);
                uint32_t addr = stA + SWZ((uint32_t)(row * 128 + ks * 32 + (lane >> 4) * 16));
                LDSM_X4(a[mt], addr);
            }
            uint32_t bf[2][4];
            #pragma unroll
            for (int np = 0; np < 2; np++) {
                int k = ks * 16 + (lane & 15);
                int n = warp_n * 32 + np * 16 + (lane >> 4) * 8;
                uint32_t addr = stB + SWZ((uint32_t)(k * 128 + n * 2));
                LDSM_X4T(bf[np], addr);
            }
            #pragma unroll
            for (int mt = 0; mt < 4; mt++)
                #pragma unroll
                for (int nt = 0; nt < 4; nt++) {
                    int np = nt >> 1, o = (nt & 1) * 2;
                    MMA16816(acc[mt][nt], a[mt], bf[np][o], bf[np][o + 1]);
                }
        }
        __syncthreads();   // compute done before next iter overwrites this buffer
    }

    #pragma unroll
    for (int mt = 0; mt < 4; mt++) {
        int rr0 = warp_m * 64 + mt * 16 + (lane >> 2);
        int rr1 = rr0 + 8;
        int r0 = q0 + rr0, r1 = q0 + rr1;
        float l0 = sL[rr0];
        float l1 = sL[rr1];
        #pragma unroll
        for (int nt = 0; nt < 4; nt++) {
            int col = d0 + warp_n * 32 + nt * 8 + (lane & 3) * 2;
            size_t p0 = ((size_t)b * NN + r0) * DD + col;
            size_t p1 = ((size_t)b * NN + r1) * DD + col;
            float2 x0 = *(const float2*)&x[p0];
            float2 x1 = *(const float2*)&x[p1];
            *(float2*)&out[p0] = make_float2(fmaf(acc[mt][nt][0], l0, x0.x),
                                             fmaf(acc[mt][nt][1], l0, x0.y));
            *(float2*)&out[p1] = make_float2(fmaf(acc[mt][nt][2], l1, x1.x),
                                             fmaf(acc[mt][nt][3], l1, x1.y));
        }
    }
}

// ---------------- K6: in-place LayerNorm on out (float4) ----------------
__global__ __launch_bounds__(256) void k_ln(float* __restrict__ out,
                                            const float* __restrict__ gamma,
                                            const float* __restrict__ beta) {
    size_t row = blockIdx.x;
    float* y = out + row * DD;
    int tid = threadIdx.x;
    float4 v = *(float4*)&y[tid * 4];
    float mu = block_sum(v.x + v.y + v.z + v.w) * (1.0f / DD);
    float dx = v.x - mu, dy = v.y - mu, dz = v.z - mu, dw = v.w - mu;
    float var = block_sum(dx * dx + dy * dy + dz * dz + dw * dw) * (1.0f / DD);
    float inv = rsqrtf(var + LN_EPS);
    float4 g = *(const float4*)&gamma[tid * 4];
    float4 be = *(const float4*)&beta[tid * 4];
    float4 o;
    o.x = dx * inv * g.x + be.x;
    o.y = dy * inv * g.y + be.y;
    o.z = dz * inv * g.z + be.z;
    o.w = dw * inv * g.w + be.w;
    *(float4*)&y[tid * 4] = o;
}

extern "C" void kernel_launch(void* const* d_in, const int* in_sizes, int n_in,
                              void* d_out, int out_size) {
    const float* x     = (const float*)d_in[0];
    const float* mask  = (const float*)d_in[1];
    const float* U     = (const float*)d_in[2];
    const float* V     = (const float*)d_in[3];
    const float* gamma = (const float*)d_in[4];
    const float* beta  = (const float*)d_in[5];
    float* out = (float*)d_out;

    cudaFuncSetAttribute(k_proj_mma, cudaFuncAttributeMaxDynamicSharedMemorySize, PSMEM);
    cudaFuncSetAttribute(k_delta_mma, cudaFuncAttributeMaxDynamicSharedMemorySize, DSMEM);

    k_prep<<<XB_BLOCKS + RF_BLOCKS + WC_BLOCKS, 256>>>(x, mask, U, V);
    k_proj_mma<<<dim3(1, BB * NN / 64, 1), 256, PSMEM>>>(mask);
    dim3 gs(NN / 128, NN / 128, BB);
    k_scores_mma<<<gs, 256>>>();
    dim3 gd(DD / 64, NN / 128, BB);
    k_delta_mma<<<gd, 128, DSMEM>>>(x, out);
    k_ln<<<BB * NN, 256>>>(out, gamma, beta);
}